// round 9
// baseline (speedup 1.0000x reference)
#include <cuda_runtime.h>
#include <cuda_bf16.h>
#include <cstdint>
#include <stdint.h>
#include <math.h>

#define Bz 8
#define Tz 4096
#define Cz 768
#define Hz 64

// global scratch (allocation-free rule)
__device__ __nv_bfloat16 g_qh[Bz * Tz * Hz];
__device__ __nv_bfloat16 g_ql[Bz * Tz * Hz];
__device__ __nv_bfloat16 g_kh[Bz * Tz * Hz];
__device__ __nv_bfloat16 g_kl[Bz * Tz * Hz];
__device__ __nv_bfloat16 g_vh[Bz * Tz * Hz];
__device__ __nv_bfloat16 g_vl[Bz * Tz * Hz];
__device__ __nv_bfloat16 g_wth[3 * Hz * Cz];   // W^T hi  [mat][h][c]
__device__ __nv_bfloat16 g_wtl[3 * Hz * Cz];   // W^T lo

// ---------------------------------------------------------------------------
// helpers
// ---------------------------------------------------------------------------
__device__ __forceinline__ uint32_t smem_u32(const void* p) {
    uint32_t a;
    asm("{ .reg .u64 t; cvta.to.shared.u64 t, %1; cvt.u32.u64 %0, t; }"
        : "=r"(a) : "l"(p));
    return a;
}
__device__ __forceinline__ void ldsm4(uint32_t* r, uint32_t a) {
    asm volatile("ldmatrix.sync.aligned.m8n8.x4.shared.b16 {%0,%1,%2,%3}, [%4];"
        : "=r"(r[0]), "=r"(r[1]), "=r"(r[2]), "=r"(r[3]) : "r"(a));
}
__device__ __forceinline__ void ldsm4t(uint32_t* r, uint32_t a) {
    asm volatile("ldmatrix.sync.aligned.m8n8.x4.trans.shared.b16 {%0,%1,%2,%3}, [%4];"
        : "=r"(r[0]), "=r"(r[1]), "=r"(r[2]), "=r"(r[3]) : "r"(a));
}
__device__ __forceinline__ void ldsm2(uint32_t* r, uint32_t a) {
    asm volatile("ldmatrix.sync.aligned.m8n8.x2.shared.b16 {%0,%1}, [%2];"
        : "=r"(r[0]), "=r"(r[1]) : "r"(a));
}
__device__ __forceinline__ void mma16816(float* d, const uint32_t* a,
                                         const uint32_t* b) {
    asm volatile(
        "mma.sync.aligned.m16n8k16.row.col.f32.bf16.bf16.f32 "
        "{%0,%1,%2,%3}, {%4,%5,%6,%7}, {%8,%9}, {%0,%1,%2,%3};"
        : "+f"(d[0]), "+f"(d[1]), "+f"(d[2]), "+f"(d[3])
        : "r"(a[0]), "r"(a[1]), "r"(a[2]), "r"(a[3]), "r"(b[0]), "r"(b[1]));
}
__device__ __forceinline__ void cp16(uint32_t dst, const void* src) {
    asm volatile("cp.async.cg.shared.global [%0], [%1], 16;"
                 :: "r"(dst), "l"(src) : "memory");
}
__device__ __forceinline__ void cpcommit() {
    asm volatile("cp.async.commit_group;" ::: "memory");
}
template <int N> __device__ __forceinline__ void cpwait() {
    asm volatile("cp.async.wait_group %0;" :: "n"(N) : "memory");
}

// split two floats into packed bf16x2 hi + lo residual
__device__ __forceinline__ void split2(float f0, float f1,
                                       uint32_t& hi, uint32_t& lo) {
    __nv_bfloat162 h = __floats2bfloat162_rn(f0, f1);
    float g0 = __low2float(h), g1 = __high2float(h);
    __nv_bfloat162 l = __floats2bfloat162_rn(f0 - g0, f1 - g1);
    hi = reinterpret_cast<uint32_t&>(h);
    lo = reinterpret_cast<uint32_t&>(l);
}
__device__ __forceinline__ void splits(float v, __nv_bfloat16& hi,
                                       __nv_bfloat16& lo) {
    hi = __float2bfloat16(v);
    lo = __float2bfloat16(v - __bfloat162float(hi));
}

// ---------------------------------------------------------------------------
// prep: W -> W^T bf16 hi/lo   grid(48)
// ---------------------------------------------------------------------------
__global__ void prep_kernel(const float* __restrict__ Wk,
                            const float* __restrict__ Wq,
                            const float* __restrict__ Wv) {
    int mat = blockIdx.x / 16;
    int slice = blockIdx.x % 16;
    const float* W = (mat == 0) ? Wq : ((mat == 1) ? Wk : Wv);
    int n = Cz * Hz / 16;
    int base = slice * n;
    for (int t = threadIdx.x; t < n; t += 256) {
        int i = base + t;
        int c = i / Hz, h = i % Hz;
        __nv_bfloat16 hi, lo;
        splits(W[i], hi, lo);
        g_wth[mat * Hz * Cz + h * Cz + c] = hi;
        g_wtl[mat * Hz * Cz + h * Cz + c] = lo;
    }
}

// ---------------------------------------------------------------------------
// projection: all 3 matrices per block; x staged/converted ONCE per k-chunk.
// ---------------------------------------------------------------------------
#define PLD 72
#define PXH 0
#define PXL 18432
#define PW  36864
#define PSMEM (36864 + 3 * 18432)

__global__ void __launch_bounds__(256) proj_kernel(const float* __restrict__ x) {
    extern __shared__ char smem[];
    uint32_t sb = smem_u32(smem);

    long row0 = (long)blockIdx.x * 128;
    int tid = threadIdx.x, wid = tid / 32, lane = tid % 32;
    int wr0 = wid * 16;
    int rr = lane % 8, grp = lane / 8;

    float acc[3][8][4] = {};

    for (int it = 0; it < 12; it++) {
        int k0 = it * 64;
        __syncthreads();
        for (int i = tid; i < 128 * 16; i += 256) {
            int r = i / 16, c4 = (i % 16) * 4;
            float4 xv = *(const float4*)&x[(row0 + r) * Cz + k0 + c4];
            uint32_t h0, l0, h1, l1;
            split2(xv.x, xv.y, h0, l0);
            split2(xv.z, xv.w, h1, l1);
            uint32_t off = (uint32_t)(r * PLD + c4) * 2;
            *(uint2*)(smem + PXH + off) = make_uint2(h0, h1);
            *(uint2*)(smem + PXL + off) = make_uint2(l0, l1);
        }
        for (int i = tid; i < 3 * 64 * 8; i += 256) {
            int mat = i / 512, rem = i % 512;
            int h = rem / 8, ch = rem % 8;
            uint32_t off = PW + mat * 18432 + (uint32_t)(h * PLD + ch * 8) * 2;
            *(uint4*)(smem + off) =
                *(const uint4*)(g_wth + mat * Hz * Cz + h * Cz + k0 + ch * 8);
            *(uint4*)(smem + off + 9216) =
                *(const uint4*)(g_wtl + mat * Hz * Cz + h * Cz + k0 + ch * 8);
        }
        __syncthreads();

        #pragma unroll
        for (int kc = 0; kc < 4; kc++) {
            uint32_t ah[4], al[4];
            uint32_t aoff = (uint32_t)((wr0 + rr + (grp & 1) * 8) * PLD
                                       + kc * 16 + (grp >> 1) * 8) * 2;
            ldsm4(ah, sb + PXH + aoff);
            ldsm4(al, sb + PXL + aoff);
            #pragma unroll
            for (int mat = 0; mat < 3; mat++) {
                uint32_t wb = sb + PW + (uint32_t)mat * 18432;
                #pragma unroll
                for (int n = 0; n < 8; n++) {
                    uint32_t bh[2], bl[2];
                    uint32_t boff = (uint32_t)((n * 8 + rr) * PLD
                                               + kc * 16 + (grp & 1) * 8) * 2;
                    ldsm2(bh, wb + boff);
                    ldsm2(bl, wb + 9216 + boff);
                    mma16816(acc[mat][n], ah, bh);
                    mma16816(acc[mat][n], ah, bl);
                    mma16816(acc[mat][n], al, bh);
                }
            }
        }
    }

    long rA = row0 + wr0 + lane / 4;
    long rB = rA + 8;
    int cb = 2 * (lane % 4);
    #pragma unroll
    for (int mat = 0; mat < 3; mat++) {
        __nv_bfloat16* outh = (mat == 0) ? g_qh : ((mat == 1) ? g_kh : g_vh);
        __nv_bfloat16* outl = (mat == 0) ? g_ql : ((mat == 1) ? g_kl : g_vl);
        float scale = (mat == 0) ? 0.03608439182435161f : 1.0f;
        #pragma unroll
        for (int n = 0; n < 8; n++) {
            uint32_t hi, lo;
            split2(acc[mat][n][0] * scale, acc[mat][n][1] * scale, hi, lo);
            *(uint32_t*)&outh[rA * Hz + n * 8 + cb] = hi;
            *(uint32_t*)&outl[rA * Hz + n * 8 + cb] = lo;
            split2(acc[mat][n][2] * scale, acc[mat][n][3] * scale, hi, lo);
            *(uint32_t*)&outh[rB * Hz + n * 8 + cb] = hi;
            *(uint32_t*)&outl[rB * Hz + n * 8 + cb] = lo;
        }
    }
}

// ---------------------------------------------------------------------------
// flash attention with intra-block split-K:
// q-tile 64 rows, 8 warps: wg = wid/4 picks k-tile parity, wr = wid%4 picks
// 16-row group. Two 64-key tiles staged & computed concurrently per step.
// Partial (m,l,O) merged via smem at end of each q-tile.
// grid (32, 8): block bx does q-tiles {bx, 63-bx}; 2 blocks/SM.
// ---------------------------------------------------------------------------
#define LDA 72
#define QS_H 0
#define QS_L 9216
#define ST0 18432
#define STG 36864            // stage stride; in-stage: Kh 0, Kl 9216, Vh 18432, Vl 27648
#define OSM 18432            // combine O region (reuses stage0)
#define MSM (18432 + 16384)  // 64 floats m
#define LSM (MSM + 256)      // 64 floats l
#define ASMEM 92160

__global__ void __launch_bounds__(256, 2) attn_kernel(float* __restrict__ out) {
    extern __shared__ char smem[];
    uint32_t sb = smem_u32(smem);

    int tid = threadIdx.x, wid = tid / 32, lane = tid % 32;
    int wg = wid >> 2;          // k-parity group
    int wr = wid & 3;           // row group
    int b = blockIdx.y;
    int rr = lane % 8, grp = lane / 8;

    const __nv_bfloat16* gsrc[4] = {
        g_kh + (long)b * Tz * Hz, g_kl + (long)b * Tz * Hz,
        g_vh + (long)b * Tz * Hz, g_vl + (long)b * Tz * Hz};

    for (int wh = 0; wh < 2; wh++) {
        int qt = wh ? (63 - (int)blockIdx.x) : (int)blockIdx.x;
        int q0 = qt * 64;
        int r0a = q0 + wr * 16;

        // ---- stage Q (64 rows, hi/lo) ----
        const __nv_bfloat16* gqh = g_qh + ((long)b * Tz + q0) * Hz;
        const __nv_bfloat16* gql = g_ql + ((long)b * Tz + q0) * Hz;
        for (int i = tid; i < 1024; i += 256) {
            int arr = i >> 9, idx = i & 511;
            int r = idx >> 3, ch = idx & 7;
            const __nv_bfloat16* src = arr ? gql : gqh;
            *(uint4*)(smem + (arr ? QS_L : QS_H) + (uint32_t)(r * LDA + ch * 8) * 2) =
                *(const uint4*)(src + r * Hz + ch * 8);
        }
        __syncthreads();

        uint32_t qfh[4][4];
        uint32_t qaoff[4];
        #pragma unroll
        for (int kc = 0; kc < 4; kc++) {
            qaoff[kc] = (uint32_t)((wr * 16 + rr + (grp & 1) * 8) * LDA
                                   + kc * 16 + (grp >> 1) * 8) * 2;
            ldsm4(qfh[kc], sb + QS_H + qaoff[kc]);
        }

        float O[8][4] = {};
        float mrow[2] = {-1e30f, -1e30f};
        float lrow[2] = {0.0f, 0.0f};

        int njt = qt + 1;
        int npair = (njt + 1) >> 1;

        for (int p = 0; p < npair; p++) {
            __syncthreads();    // previous pair fully consumed
            int jA = 2 * p, jB = 2 * p + 1;
            // stage tile jA -> stage0, jB -> stage1
            for (int i = tid; i < 2048; i += 256) {
                int arr = i >> 9, idx = i & 511;
                int r = idx >> 3, ch = idx & 7;
                cp16(sb + ST0 + arr * 9216 + (uint32_t)(r * LDA + ch * 8) * 2,
                     gsrc[arr] + (long)(jA * 64 + r) * Hz + ch * 8);
            }
            if (jB < njt) {
                for (int i = tid; i < 2048; i += 256) {
                    int arr = i >> 9, idx = i & 511;
                    int r = idx >> 3, ch = idx & 7;
                    cp16(sb + ST0 + STG + arr * 9216 + (uint32_t)(r * LDA + ch * 8) * 2,
                         gsrc[arr] + (long)(jB * 64 + r) * Hz + ch * 8);
                }
            }
            cpcommit();
            cpwait<0>();
            __syncthreads();

            int j = 2 * p + wg;
            int kb = j * 64;
            if (j < njt && kb <= r0a + 15) {
                uint32_t base = sb + ST0 + (uint32_t)wg * STG;

                // reload ql fragments (register saver)
                uint32_t qfl[4][4];
                #pragma unroll
                for (int kc = 0; kc < 4; kc++)
                    ldsm4(qfl[kc], sb + QS_L + qaoff[kc]);

                // ---- S = Q K^T over 64 keys ----
                float S[8][4] = {};
                #pragma unroll
                for (int np = 0; np < 4; np++) {
                    #pragma unroll
                    for (int kc = 0; kc < 4; kc++) {
                        uint32_t row = (uint32_t)(np * 16 + ((grp >> 1) ? 8 : 0) + rr);
                        uint32_t col = (uint32_t)(kc * 16 + (grp & 1) * 8);
                        uint32_t off = (row * LDA + col) * 2;
                        uint32_t bh[4], bl[4];
                        ldsm4(bh, base + off);
                        ldsm4(bl, base + 9216 + off);
                        mma16816(S[np * 2], qfh[kc], bh);
                        mma16816(S[np * 2], qfl[kc], bh);
                        mma16816(S[np * 2], qfh[kc], bl);
                        mma16816(S[np * 2 + 1], qfh[kc], bh + 2);
                        mma16816(S[np * 2 + 1], qfl[kc], bh + 2);
                        mma16816(S[np * 2 + 1], qfh[kc], bl + 2);
                    }
                }

                // ---- causal mask ----
                int rA = r0a + lane / 4;
                int rB = rA + 8;
                if (kb + 63 > r0a) {
                    #pragma unroll
                    for (int n = 0; n < 8; n++) {
                        int c0 = kb + n * 8 + 2 * (lane % 4);
                        if (c0 > rA)     S[n][0] = -1e30f;
                        if (c0 + 1 > rA) S[n][1] = -1e30f;
                        if (c0 > rB)     S[n][2] = -1e30f;
                        if (c0 + 1 > rB) S[n][3] = -1e30f;
                    }
                }

                // ---- online softmax (partial) ----
                float mA = -1e30f, mB = -1e30f;
                #pragma unroll
                for (int n = 0; n < 8; n++) {
                    mA = fmaxf(mA, fmaxf(S[n][0], S[n][1]));
                    mB = fmaxf(mB, fmaxf(S[n][2], S[n][3]));
                }
                #pragma unroll
                for (int off = 1; off < 4; off <<= 1) {
                    mA = fmaxf(mA, __shfl_xor_sync(0xffffffffu, mA, off));
                    mB = fmaxf(mB, __shfl_xor_sync(0xffffffffu, mB, off));
                }
                float mnA = fmaxf(mrow[0], mA), mnB = fmaxf(mrow[1], mB);
                float aA = __expf(mrow[0] - mnA), aB = __expf(mrow[1] - mnB);
                mrow[0] = mnA; mrow[1] = mnB;
                float sA = 0.0f, sB = 0.0f;
                #pragma unroll
                for (int n = 0; n < 8; n++) {
                    S[n][0] = __expf(S[n][0] - mnA); sA += S[n][0];
                    S[n][1] = __expf(S[n][1] - mnA); sA += S[n][1];
                    S[n][2] = __expf(S[n][2] - mnB); sB += S[n][2];
                    S[n][3] = __expf(S[n][3] - mnB); sB += S[n][3];
                }
                #pragma unroll
                for (int off = 1; off < 4; off <<= 1) {
                    sA += __shfl_xor_sync(0xffffffffu, sA, off);
                    sB += __shfl_xor_sync(0xffffffffu, sB, off);
                }
                lrow[0] = lrow[0] * aA + sA;
                lrow[1] = lrow[1] * aB + sB;
                #pragma unroll
                for (int n = 0; n < 8; n++) {
                    O[n][0] *= aA; O[n][1] *= aA; O[n][2] *= aB; O[n][3] *= aB;
                }

                // ---- O += P V ----
                #pragma unroll
                for (int kc = 0; kc < 4; kc++) {
                    int t0 = 2 * kc, t1 = 2 * kc + 1;
                    uint32_t ph[4], pl[4];
                    split2(S[t0][0], S[t0][1], ph[0], pl[0]);
                    split2(S[t0][2], S[t0][3], ph[1], pl[1]);
                    split2(S[t1][0], S[t1][1], ph[2], pl[2]);
                    split2(S[t1][2], S[t1][3], ph[3], pl[3]);
                    #pragma unroll
                    for (int np = 0; np < 4; np++) {
                        uint32_t row = (uint32_t)(kc * 16 + ((grp & 1) ? 8 : 0) + rr);
                        uint32_t col = (uint32_t)(np * 16 + (grp >> 1) * 8);
                        uint32_t off = (row * LDA + col) * 2;
                        uint32_t vh[4], vl[4];
                        ldsm4t(vh, base + 18432 + off);
                        ldsm4t(vl, base + 27648 + off);
                        mma16816(O[np * 2], ph, vh);
                        mma16816(O[np * 2], pl, vh);
                        mma16816(O[np * 2], ph, vl);
                        mma16816(O[np * 2 + 1], ph, vh + 2);
                        mma16816(O[np * 2 + 1], pl, vh + 2);
                        mma16816(O[np * 2 + 1], ph, vl + 2);
                    }
                }
            }
        }

        // ---- combine partials of wg0/wg1 ----
        __syncthreads();
        float* OS = (float*)(smem + OSM);
        float* MS = (float*)(smem + MSM);
        float* LS = (float*)(smem + LSM);
        int rA_l = lane / 4;
        int cb = 2 * (lane % 4);
        if (wg == 1) {
            float* myO = OS + wr * 1024;
            #pragma unroll
            for (int n = 0; n < 8; n++) {
                myO[rA_l * 64 + n * 8 + cb]       = O[n][0];
                myO[rA_l * 64 + n * 8 + cb + 1]   = O[n][1];
                myO[(rA_l + 8) * 64 + n * 8 + cb]     = O[n][2];
                myO[(rA_l + 8) * 64 + n * 8 + cb + 1] = O[n][3];
            }
            if ((lane & 3) == 0) {
                MS[wr * 16 + rA_l] = mrow[0];
                MS[wr * 16 + rA_l + 8] = mrow[1];
                LS[wr * 16 + rA_l] = lrow[0];
                LS[wr * 16 + rA_l + 8] = lrow[1];
            }
        }
        __syncthreads();
        if (wg == 0) {
            float m1A = MS[wr * 16 + rA_l], m1B = MS[wr * 16 + rA_l + 8];
            float l1A = LS[wr * 16 + rA_l], l1B = LS[wr * 16 + rA_l + 8];
            float msA = fmaxf(mrow[0], m1A), msB = fmaxf(mrow[1], m1B);
            float a0A = __expf(mrow[0] - msA), a1A = __expf(m1A - msA);
            float a0B = __expf(mrow[1] - msB), a1B = __expf(m1B - msB);
            float lA = lrow[0] * a0A + l1A * a1A;
            float lB = lrow[1] * a0B + l1B * a1B;
            float invA = 1.0f / lA, invB = 1.0f / lB;
            float* myO = OS + wr * 1024;
            long gA = (long)b * Tz + r0a + rA_l;
            long gB = gA + 8;
            #pragma unroll
            for (int n = 0; n < 8; n++) {
                float o0 = O[n][0] * a0A + myO[rA_l * 64 + n * 8 + cb] * a1A;
                float o1 = O[n][1] * a0A + myO[rA_l * 64 + n * 8 + cb + 1] * a1A;
                float o2 = O[n][2] * a0B + myO[(rA_l + 8) * 64 + n * 8 + cb] * a1B;
                float o3 = O[n][3] * a0B + myO[(rA_l + 8) * 64 + n * 8 + cb + 1] * a1B;
                *(float2*)&out[gA * Hz + n * 8 + cb] = make_float2(o0 * invA, o1 * invA);
                *(float2*)&out[gB * Hz + n * 8 + cb] = make_float2(o2 * invB, o3 * invB);
            }
        }
        __syncthreads();   // smem free before next q-tile
    }
}

extern "C" void kernel_launch(void* const* d_in, const int* in_sizes, int n_in,
                              void* d_out, int out_size) {
    const float* x  = (const float*)d_in[0];
    const float* Wk = (const float*)d_in[1];
    const float* Wq = (const float*)d_in[2];
    const float* Wv = (const float*)d_in[3];
    float* out = (float*)d_out;

    prep_kernel<<<48, 256>>>(Wk, Wq, Wv);

    cudaFuncSetAttribute(proj_kernel,
                         cudaFuncAttributeMaxDynamicSharedMemorySize, PSMEM);
    proj_kernel<<<(Bz * Tz) / 128, 256, PSMEM>>>(x);

    cudaFuncSetAttribute(attn_kernel,
                         cudaFuncAttributeMaxDynamicSharedMemorySize, ASMEM);
    dim3 ag(32, Bz);
    attn_kernel<<<ag, 256, ASMEM>>>(out);
}

// round 11
// speedup vs baseline: 1.3579x; 1.3579x over previous
#include <cuda_runtime.h>
#include <cuda_fp16.h>
#include <cstdint>
#include <stdint.h>
#include <math.h>

#define Bz 8
#define Tz 4096
#define Cz 768
#define Hz 64

// global scratch (allocation-free rule) — fp16 q/k/v, fp16 W^T hi/lo
__device__ __half g_q16[Bz * Tz * Hz];
__device__ __half g_k16[Bz * Tz * Hz];
__device__ __half g_v16[Bz * Tz * Hz];
__device__ __half g_wth[3 * Hz * Cz];
__device__ __half g_wtl[3 * Hz * Cz];

// ---------------------------------------------------------------------------
// helpers
// ---------------------------------------------------------------------------
__device__ __forceinline__ uint32_t smem_u32(const void* p) {
    uint32_t a;
    asm("{ .reg .u64 t; cvta.to.shared.u64 t, %1; cvt.u32.u64 %0, t; }"
        : "=r"(a) : "l"(p));
    return a;
}
__device__ __forceinline__ void ldsm4(uint32_t* r, uint32_t a) {
    asm volatile("ldmatrix.sync.aligned.m8n8.x4.shared.b16 {%0,%1,%2,%3}, [%4];"
        : "=r"(r[0]), "=r"(r[1]), "=r"(r[2]), "=r"(r[3]) : "r"(a));
}
__device__ __forceinline__ void ldsm4t(uint32_t* r, uint32_t a) {
    asm volatile("ldmatrix.sync.aligned.m8n8.x4.trans.shared.b16 {%0,%1,%2,%3}, [%4];"
        : "=r"(r[0]), "=r"(r[1]), "=r"(r[2]), "=r"(r[3]) : "r"(a));
}
__device__ __forceinline__ void ldsm2(uint32_t* r, uint32_t a) {
    asm volatile("ldmatrix.sync.aligned.m8n8.x2.shared.b16 {%0,%1}, [%2];"
        : "=r"(r[0]), "=r"(r[1]) : "r"(a));
}
__device__ __forceinline__ void mma16816(float* d, const uint32_t* a,
                                         const uint32_t* b) {
    asm volatile(
        "mma.sync.aligned.m16n8k16.row.col.f32.f16.f16.f32 "
        "{%0,%1,%2,%3}, {%4,%5,%6,%7}, {%8,%9}, {%0,%1,%2,%3};"
        : "+f"(d[0]), "+f"(d[1]), "+f"(d[2]), "+f"(d[3])
        : "r"(a[0]), "r"(a[1]), "r"(a[2]), "r"(a[3]), "r"(b[0]), "r"(b[1]));
}
__device__ __forceinline__ void cp16(uint32_t dst, const void* src) {
    asm volatile("cp.async.cg.shared.global [%0], [%1], 16;"
                 :: "r"(dst), "l"(src) : "memory");
}
__device__ __forceinline__ void cpcommit() {
    asm volatile("cp.async.commit_group;" ::: "memory");
}
template <int N> __device__ __forceinline__ void cpwait() {
    asm volatile("cp.async.wait_group %0;" :: "n"(N) : "memory");
}
__device__ __forceinline__ float ex2(float x) {
    float y;
    asm("ex2.approx.f32 %0, %1;" : "=f"(y) : "f"(x));
    return y;
}
__device__ __forceinline__ uint32_t packh2(float a, float b) {
    __half2 h = __floats2half2_rn(a, b);
    return reinterpret_cast<uint32_t&>(h);
}
__device__ __forceinline__ void splith(float v, __half& hi, __half& lo) {
    hi = __float2half(v);
    lo = __float2half(v - __half2float(hi));
}

// log2(e) folded into the attention scale: 768^-0.5 * 1.4426950408889634
#define QSCALE 0.052057446116f

// ---------------------------------------------------------------------------
// prep: W -> W^T fp16 hi/lo   grid(48)
// ---------------------------------------------------------------------------
__global__ void prep_kernel(const float* __restrict__ Wk,
                            const float* __restrict__ Wq,
                            const float* __restrict__ Wv) {
    int mat = blockIdx.x / 16;
    int slice = blockIdx.x % 16;
    const float* W = (mat == 0) ? Wq : ((mat == 1) ? Wk : Wv);
    int n = Cz * Hz / 16;
    int base = slice * n;
    for (int t = threadIdx.x; t < n; t += 256) {
        int i = base + t;
        int c = i / Hz, h = i % Hz;
        __half hi, lo;
        splith(W[i], hi, lo);
        g_wth[mat * Hz * Cz + h * Cz + c] = hi;
        g_wtl[mat * Hz * Cz + h * Cz + c] = lo;
    }
}

// ---------------------------------------------------------------------------
// projection: all 3 mats per block; 2-term fp16 (x single, W hi/lo).
// grid (256), 256 threads, 8 warps x 16 rows, k-chunks of 64.
// smem: x [128x72] fp16 + per-mat W hi/lo [64x72] fp16
// ---------------------------------------------------------------------------
#define PLD 72
#define PX 0
#define PW 18432          // + mat*18432 (hi), +9216 (lo)
#define PSMEM (18432 + 3 * 18432)   // 73728

__global__ void __launch_bounds__(256) proj_kernel(const float* __restrict__ x) {
    extern __shared__ char smem[];
    uint32_t sb = smem_u32(smem);

    long row0 = (long)blockIdx.x * 128;
    int tid = threadIdx.x, wid = tid / 32, lane = tid % 32;
    int wr0 = wid * 16;
    int rr = lane % 8, grp = lane / 8;

    float acc[3][8][4] = {};

    for (int it = 0; it < 12; it++) {
        int k0 = it * 64;
        __syncthreads();
        // stage x -> fp16 (single), 8 halfs per thread-iter
        for (int i = tid; i < 128 * 8; i += 256) {
            int r = i / 8, ch = i % 8;
            const float* src = &x[(row0 + r) * Cz + k0 + ch * 8];
            float4 a = *(const float4*)src;
            float4 b = *(const float4*)(src + 4);
            uint4 v;
            v.x = packh2(a.x, a.y);
            v.y = packh2(a.z, a.w);
            v.z = packh2(b.x, b.y);
            v.w = packh2(b.z, b.w);
            *(uint4*)(smem + PX + (uint32_t)(r * PLD + ch * 8) * 2) = v;
        }
        // stage W^T hi/lo for all 3 mats (already fp16)
        for (int i = tid; i < 3 * 64 * 8; i += 256) {
            int mat = i / 512, rem = i % 512;
            int h = rem / 8, ch = rem % 8;
            uint32_t off = PW + mat * 18432 + (uint32_t)(h * PLD + ch * 8) * 2;
            *(uint4*)(smem + off) =
                *(const uint4*)(g_wth + mat * Hz * Cz + h * Cz + k0 + ch * 8);
            *(uint4*)(smem + off + 9216) =
                *(const uint4*)(g_wtl + mat * Hz * Cz + h * Cz + k0 + ch * 8);
        }
        __syncthreads();

        #pragma unroll
        for (int kc = 0; kc < 4; kc++) {
            uint32_t xa[4];
            uint32_t aoff = (uint32_t)((wr0 + rr + (grp & 1) * 8) * PLD
                                       + kc * 16 + (grp >> 1) * 8) * 2;
            ldsm4(xa, sb + PX + aoff);
            #pragma unroll
            for (int mat = 0; mat < 3; mat++) {
                uint32_t wb = sb + PW + (uint32_t)mat * 18432;
                #pragma unroll
                for (int n = 0; n < 8; n++) {
                    uint32_t bh[2], bl[2];
                    uint32_t boff = (uint32_t)((n * 8 + rr) * PLD
                                               + kc * 16 + (grp & 1) * 8) * 2;
                    ldsm2(bh, wb + boff);
                    ldsm2(bl, wb + 9216 + boff);
                    mma16816(acc[mat][n], xa, bh);
                    mma16816(acc[mat][n], xa, bl);
                }
            }
        }
    }

    long rA = row0 + wr0 + lane / 4;
    long rB = rA + 8;
    int cb = 2 * (lane % 4);
    #pragma unroll
    for (int mat = 0; mat < 3; mat++) {
        __half* outp = (mat == 0) ? g_q16 : ((mat == 1) ? g_k16 : g_v16);
        float scale = (mat == 0) ? QSCALE : 1.0f;
        #pragma unroll
        for (int n = 0; n < 8; n++) {
            *(uint32_t*)&outp[rA * Hz + n * 8 + cb] =
                packh2(acc[mat][n][0] * scale, acc[mat][n][1] * scale);
            *(uint32_t*)&outp[rB * Hz + n * 8 + cb] =
                packh2(acc[mat][n][2] * scale, acc[mat][n][3] * scale);
        }
    }
}

// ---------------------------------------------------------------------------
// flash attention: single-term fp16 mma, q-tile 128, k-tile 128 (2x64 halves),
// cp.async double buffer, exp2-domain softmax.
// grid (32, B), longest q-tiles first; 2 blocks/SM.
// ---------------------------------------------------------------------------
#define LDA 72
#define QS 0
#define ST0 18432
#define STG 36864           // stage stride; in-stage: K 0, V 18432
#define ASMEM (18432 + 2 * 36864)   // 92160

__global__ void __launch_bounds__(256, 2) attn_kernel(float* __restrict__ out) {
    extern __shared__ char smem[];
    uint32_t sb = smem_u32(smem);

    int tid = threadIdx.x, wid = tid / 32, lane = tid % 32;
    int b = blockIdx.y;
    int qt = 31 - (int)blockIdx.x;   // longest first
    int q0 = qt * 128;
    int rr = lane % 8, grp = lane / 8;
    int wr0 = wid * 16;
    int r0a = q0 + wr0;

    const __half* gq = g_q16 + ((long)b * Tz + q0) * Hz;
    const __half* gk = g_k16 + (long)b * Tz * Hz;
    const __half* gv = g_v16 + (long)b * Tz * Hz;

    // ---- stage Q (128 rows fp16) ----
    for (int i = tid; i < 1024; i += 256) {
        int r = i >> 3, ch = i & 7;
        *(uint4*)(smem + QS + (uint32_t)(r * LDA + ch * 8) * 2) =
            *(const uint4*)(gq + r * Hz + ch * 8);
    }
    __syncthreads();

    uint32_t qf[4][4];
    #pragma unroll
    for (int kc = 0; kc < 4; kc++) {
        uint32_t aoff = (uint32_t)((wr0 + rr + (grp & 1) * 8) * LDA
                                   + kc * 16 + (grp >> 1) * 8) * 2;
        ldsm4(qf[kc], sb + QS + aoff);
    }

    float O[8][4] = {};
    float mrow[2] = {-1e30f, -1e30f};
    float lrow[2] = {0.0f, 0.0f};

    int njt = qt + 1;

    // prologue: stage tile 0 into stage0 (K 1024 + V 1024 cp16)
    for (int i = tid; i < 2048; i += 256) {
        int arr = i >> 10, idx = i & 1023;
        int r = idx >> 3, ch = idx & 7;
        const __half* src = arr ? gv : gk;
        cp16(sb + ST0 + arr * 18432 + (uint32_t)(r * LDA + ch * 8) * 2,
             src + (long)r * Hz + ch * 8);
    }
    cpcommit();

    for (int j = 0; j < njt; j++) {
        uint32_t bufc = sb + ST0 + (uint32_t)(j & 1) * STG;
        if (j + 1 < njt) {
            uint32_t bufn = sb + ST0 + (uint32_t)((j + 1) & 1) * STG;
            int jb = (j + 1) * 128;
            for (int i = tid; i < 2048; i += 256) {
                int arr = i >> 10, idx = i & 1023;
                int r = idx >> 3, ch = idx & 7;
                const __half* src = arr ? gv : gk;
                cp16(bufn + arr * 18432 + (uint32_t)(r * LDA + ch * 8) * 2,
                     src + (long)(jb + r) * Hz + ch * 8);
            }
            cpcommit();
            cpwait<1>();
        } else {
            cpwait<0>();
        }
        __syncthreads();

        #pragma unroll
        for (int half = 0; half < 2; half++) {
            int kb = j * 128 + half * 64;
            if (kb > r0a + 15) break;      // fully masked for this warp
            uint32_t rbase = (uint32_t)(half * 64);

            // ---- S = Q K^T (single-term fp16) ----
            float S[8][4] = {};
            #pragma unroll
            for (int np = 0; np < 4; np++) {
                #pragma unroll
                for (int kc = 0; kc < 4; kc++) {
                    uint32_t row = rbase + (uint32_t)(np * 16 + ((grp >> 1) ? 8 : 0) + rr);
                    uint32_t col = (uint32_t)(kc * 16 + (grp & 1) * 8);
                    uint32_t bh[4];
                    ldsm4(bh, bufc + (row * LDA + col) * 2);
                    mma16816(S[np * 2], qf[kc], bh);
                    mma16816(S[np * 2 + 1], qf[kc], bh + 2);
                }
            }

            // ---- causal mask ----
            int rA = r0a + lane / 4;
            int rB = rA + 8;
            if (kb + 63 > r0a) {
                #pragma unroll
                for (int n = 0; n < 8; n++) {
                    int c0 = kb + n * 8 + 2 * (lane % 4);
                    if (c0 > rA)     S[n][0] = -1e30f;
                    if (c0 + 1 > rA) S[n][1] = -1e30f;
                    if (c0 > rB)     S[n][2] = -1e30f;
                    if (c0 + 1 > rB) S[n][3] = -1e30f;
                }
            }

            // ---- online softmax (exp2 domain) ----
            float mA = -1e30f, mB = -1e30f;
            #pragma unroll
            for (int n = 0; n < 8; n++) {
                mA = fmaxf(mA, fmaxf(S[n][0], S[n][1]));
                mB = fmaxf(mB, fmaxf(S[n][2], S[n][3]));
            }
            #pragma unroll
            for (int off = 1; off < 4; off <<= 1) {
                mA = fmaxf(mA, __shfl_xor_sync(0xffffffffu, mA, off));
                mB = fmaxf(mB, __shfl_xor_sync(0xffffffffu, mB, off));
            }
            float mnA = fmaxf(mrow[0], mA), mnB = fmaxf(mrow[1], mB);
            float aA = ex2(mrow[0] - mnA), aB = ex2(mrow[1] - mnB);
            mrow[0] = mnA; mrow[1] = mnB;
            float sA = 0.0f, sB = 0.0f;
            #pragma unroll
            for (int n = 0; n < 8; n++) {
                S[n][0] = ex2(S[n][0] - mnA); sA += S[n][0];
                S[n][1] = ex2(S[n][1] - mnA); sA += S[n][1];
                S[n][2] = ex2(S[n][2] - mnB); sB += S[n][2];
                S[n][3] = ex2(S[n][3] - mnB); sB += S[n][3];
            }
            #pragma unroll
            for (int off = 1; off < 4; off <<= 1) {
                sA += __shfl_xor_sync(0xffffffffu, sA, off);
                sB += __shfl_xor_sync(0xffffffffu, sB, off);
            }
            lrow[0] = lrow[0] * aA + sA;
            lrow[1] = lrow[1] * aB + sB;
            #pragma unroll
            for (int n = 0; n < 8; n++) {
                O[n][0] *= aA; O[n][1] *= aA; O[n][2] *= aB; O[n][3] *= aB;
            }

            // ---- O += P V (single-term fp16) ----
            #pragma unroll
            for (int kc = 0; kc < 4; kc++) {
                int t0 = 2 * kc, t1 = 2 * kc + 1;
                uint32_t ph[4];
                ph[0] = packh2(S[t0][0], S[t0][1]);
                ph[1] = packh2(S[t0][2], S[t0][3]);
                ph[2] = packh2(S[t1][0], S[t1][1]);
                ph[3] = packh2(S[t1][2], S[t1][3]);
                #pragma unroll
                for (int np = 0; np < 4; np++) {
                    uint32_t row = rbase + (uint32_t)(kc * 16 + ((grp & 1) ? 8 : 0) + rr);
                    uint32_t col = (uint32_t)(np * 16 + (grp >> 1) * 8);
                    uint32_t vh[4];
                    ldsm4t(vh, bufc + 18432 + (row * LDA + col) * 2);
                    mma16816(O[np * 2], ph, vh);
                    mma16816(O[np * 2 + 1], ph, vh + 2);
                }
            }
        }
        __syncthreads();   // all warps done with bufc before it is refilled
    }

    // epilogue
    float invA = 1.0f / lrow[0];
    float invB = 1.0f / lrow[1];
    long rA = (long)b * Tz + r0a + lane / 4;
    long rB = rA + 8;
    int cb = 2 * (lane % 4);
    #pragma unroll
    for (int n = 0; n < 8; n++) {
        *(float2*)&out[rA * Hz + n * 8 + cb] =
            make_float2(O[n][0] * invA, O[n][1] * invA);
        *(float2*)&out[rB * Hz + n * 8 + cb] =
            make_float2(O[n][2] * invB, O[n][3] * invB);
    }
}

extern "C" void kernel_launch(void* const* d_in, const int* in_sizes, int n_in,
                              void* d_out, int out_size) {
    const float* x  = (const float*)d_in[0];
    const float* Wk = (const float*)d_in[1];
    const float* Wq = (const float*)d_in[2];
    const float* Wv = (const float*)d_in[3];
    float* out = (float*)d_out;

    prep_kernel<<<48, 256>>>(Wk, Wq, Wv);

    cudaFuncSetAttribute(proj_kernel,
                         cudaFuncAttributeMaxDynamicSharedMemorySize, PSMEM);
    proj_kernel<<<(Bz * Tz) / 128, 256, PSMEM>>>(x);

    cudaFuncSetAttribute(attn_kernel,
                         cudaFuncAttributeMaxDynamicSharedMemorySize, ASMEM);
    dim3 ag(32, Bz);
    attn_kernel<<<ag, 256, ASMEM>>>(out);
}

// round 15
// speedup vs baseline: 1.5875x; 1.1691x over previous
#include <cuda_runtime.h>
#include <cuda_fp16.h>
#include <cstdint>
#include <stdint.h>
#include <math.h>

#define Bz 8
#define Tz 4096
#define Cz 768
#define Hz 64

// global scratch (allocation-free rule)
__device__ __half g_q16[Bz * Tz * Hz];
__device__ __half g_k16[Bz * Tz * Hz];
__device__ __half g_v16[Bz * Tz * Hz];
__device__ __half g_wth[3 * Hz * Cz];
__device__ __half g_wtl[3 * Hz * Cz];
// split-K partials: [part][b][t][h] and [part][b][t]
__device__ float g_po[2 * Bz * Tz * Hz];
__device__ float g_pm[2 * Bz * Tz];
__device__ float g_pl[2 * Bz * Tz];

// ---------------------------------------------------------------------------
// helpers
// ---------------------------------------------------------------------------
__device__ __forceinline__ uint32_t smem_u32(const void* p) {
    uint32_t a;
    asm("{ .reg .u64 t; cvta.to.shared.u64 t, %1; cvt.u32.u64 %0, t; }"
        : "=r"(a) : "l"(p));
    return a;
}
__device__ __forceinline__ void ldsm4(uint32_t* r, uint32_t a) {
    asm volatile("ldmatrix.sync.aligned.m8n8.x4.shared.b16 {%0,%1,%2,%3}, [%4];"
        : "=r"(r[0]), "=r"(r[1]), "=r"(r[2]), "=r"(r[3]) : "r"(a));
}
__device__ __forceinline__ void ldsm4t(uint32_t* r, uint32_t a) {
    asm volatile("ldmatrix.sync.aligned.m8n8.x4.trans.shared.b16 {%0,%1,%2,%3}, [%4];"
        : "=r"(r[0]), "=r"(r[1]), "=r"(r[2]), "=r"(r[3]) : "r"(a));
}
__device__ __forceinline__ void ldsm2(uint32_t* r, uint32_t a) {
    asm volatile("ldmatrix.sync.aligned.m8n8.x2.shared.b16 {%0,%1}, [%2];"
        : "=r"(r[0]), "=r"(r[1]) : "r"(a));
}
__device__ __forceinline__ void mma16816(float* d, const uint32_t* a,
                                         const uint32_t* b) {
    asm volatile(
        "mma.sync.aligned.m16n8k16.row.col.f32.f16.f16.f32 "
        "{%0,%1,%2,%3}, {%4,%5,%6,%7}, {%8,%9}, {%0,%1,%2,%3};"
        : "+f"(d[0]), "+f"(d[1]), "+f"(d[2]), "+f"(d[3])
        : "r"(a[0]), "r"(a[1]), "r"(a[2]), "r"(a[3]), "r"(b[0]), "r"(b[1]));
}
__device__ __forceinline__ void cp16(uint32_t dst, const void* src) {
    asm volatile("cp.async.cg.shared.global [%0], [%1], 16;"
                 :: "r"(dst), "l"(src) : "memory");
}
__device__ __forceinline__ void cpcommit() {
    asm volatile("cp.async.commit_group;" ::: "memory");
}
template <int N> __device__ __forceinline__ void cpwait() {
    asm volatile("cp.async.wait_group %0;" :: "n"(N) : "memory");
}
__device__ __forceinline__ float ex2(float x) {
    float y;
    asm("ex2.approx.f32 %0, %1;" : "=f"(y) : "f"(x));
    return y;
}
__device__ __forceinline__ uint32_t packh2(float a, float b) {
    __half2 h = __floats2half2_rn(a, b);
    return reinterpret_cast<uint32_t&>(h);
}
__device__ __forceinline__ void splith(float v, __half& hi, __half& lo) {
    hi = __float2half(v);
    lo = __float2half(v - __half2float(hi));
}

// log2(e) folded into the attention scale: 768^-0.5 * log2(e)
#define QSCALE 0.052057446116f

// ---------------------------------------------------------------------------
// prep: W -> W^T fp16 hi/lo   grid(48)
// ---------------------------------------------------------------------------
__global__ void prep_kernel(const float* __restrict__ Wk,
                            const float* __restrict__ Wq,
                            const float* __restrict__ Wv) {
    int mat = blockIdx.x / 16;
    int slice = blockIdx.x % 16;
    const float* W = (mat == 0) ? Wq : ((mat == 1) ? Wk : Wv);
    int n = Cz * Hz / 16;
    int base = slice * n;
    for (int t = threadIdx.x; t < n; t += 256) {
        int i = base + t;
        int c = i / Hz, h = i % Hz;
        __half hi, lo;
        splith(W[i], hi, lo);
        g_wth[mat * Hz * Cz + h * Cz + c] = hi;
        g_wtl[mat * Hz * Cz + h * Cz + c] = lo;
    }
}

// ---------------------------------------------------------------------------
// projection: all 3 mats per block; 2-term fp16 (x single, W hi/lo).
// ---------------------------------------------------------------------------
#define PLD 72
#define PX 0
#define PW 18432
#define PSMEM (18432 + 3 * 18432)

__global__ void __launch_bounds__(256) proj_kernel(const float* __restrict__ x) {
    extern __shared__ char smem[];
    uint32_t sb = smem_u32(smem);

    long row0 = (long)blockIdx.x * 128;
    int tid = threadIdx.x, wid = tid / 32, lane = tid % 32;
    int wr0 = wid * 16;
    int rr = lane % 8, grp = lane / 8;

    float acc[3][8][4] = {};

    for (int it = 0; it < 12; it++) {
        int k0 = it * 64;
        __syncthreads();
        for (int i = tid; i < 128 * 8; i += 256) {
            int r = i / 8, ch = i % 8;
            const float* src = &x[(row0 + r) * Cz + k0 + ch * 8];
            float4 a = *(const float4*)src;
            float4 b = *(const float4*)(src + 4);
            uint4 v;
            v.x = packh2(a.x, a.y);
            v.y = packh2(a.z, a.w);
            v.z = packh2(b.x, b.y);
            v.w = packh2(b.z, b.w);
            *(uint4*)(smem + PX + (uint32_t)(r * PLD + ch * 8) * 2) = v;
        }
        for (int i = tid; i < 3 * 64 * 8; i += 256) {
            int mat = i / 512, rem = i % 512;
            int h = rem / 8, ch = rem % 8;
            uint32_t off = PW + mat * 18432 + (uint32_t)(h * PLD + ch * 8) * 2;
            *(uint4*)(smem + off) =
                *(const uint4*)(g_wth + mat * Hz * Cz + h * Cz + k0 + ch * 8);
            *(uint4*)(smem + off + 9216) =
                *(const uint4*)(g_wtl + mat * Hz * Cz + h * Cz + k0 + ch * 8);
        }
        __syncthreads();

        #pragma unroll
        for (int kc = 0; kc < 4; kc++) {
            uint32_t xa[4];
            uint32_t aoff = (uint32_t)((wr0 + rr + (grp & 1) * 8) * PLD
                                       + kc * 16 + (grp >> 1) * 8) * 2;
            ldsm4(xa, sb + PX + aoff);
            #pragma unroll
            for (int mat = 0; mat < 3; mat++) {
                uint32_t wb = sb + PW + (uint32_t)mat * 18432;
                #pragma unroll
                for (int n = 0; n < 8; n++) {
                    uint32_t bh[2], bl[2];
                    uint32_t boff = (uint32_t)((n * 8 + rr) * PLD
                                               + kc * 16 + (grp & 1) * 8) * 2;
                    ldsm2(bh, wb + boff);
                    ldsm2(bl, wb + 9216 + boff);
                    mma16816(acc[mat][n], xa, bh);
                    mma16816(acc[mat][n], xa, bl);
                }
            }
        }
    }

    long rA = row0 + wr0 + lane / 4;
    long rB = rA + 8;
    int cb = 2 * (lane % 4);
    #pragma unroll
    for (int mat = 0; mat < 3; mat++) {
        __half* outp = (mat == 0) ? g_q16 : ((mat == 1) ? g_k16 : g_v16);
        float scale = (mat == 0) ? QSCALE : 1.0f;
        #pragma unroll
        for (int n = 0; n < 8; n++) {
            *(uint32_t*)&outp[rA * Hz + n * 8 + cb] =
                packh2(acc[mat][n][0] * scale, acc[mat][n][1] * scale);
            *(uint32_t*)&outp[rB * Hz + n * 8 + cb] =
                packh2(acc[mat][n][2] * scale, acc[mat][n][3] * scale);
        }
    }
}

// ---------------------------------------------------------------------------
// flash attention with cross-block split-K:
// grid (64, B): bx -> qt = 31 - bx/2 (longest first), part = bx & 1.
// part0 does j in [0, ceil(njt/2)), part1 the rest. Partial (O,m,l) -> scratch.
// ---------------------------------------------------------------------------
#define LDA 72
#define QS 0
#define ST0 18432
#define STG 36864
#define ASMEM (18432 + 2 * 36864)   // 92160

__global__ void __launch_bounds__(256, 2) attn_kernel() {
    extern __shared__ char smem[];
    uint32_t sb = smem_u32(smem);

    int tid = threadIdx.x, wid = tid / 32, lane = tid % 32;
    int b = blockIdx.y;
    int qt = 31 - ((int)blockIdx.x >> 1);
    int part = (int)blockIdx.x & 1;
    int q0 = qt * 128;
    int rr = lane % 8, grp = lane / 8;
    int wr0 = wid * 16;
    int r0a = q0 + wr0;

    int njt = qt + 1;
    int nj0 = (njt + 1) >> 1;
    int lo = part ? nj0 : 0;
    int hi = part ? njt : nj0;

    const __half* gq = g_q16 + ((long)b * Tz + q0) * Hz;
    const __half* gk = g_k16 + (long)b * Tz * Hz;
    const __half* gv = g_v16 + (long)b * Tz * Hz;

    float O[8][4] = {};
    float mrow[2] = {-1e30f, -1e30f};
    float lrow[2] = {0.0f, 0.0f};

    if (lo < hi) {
        // ---- stage Q (128 rows fp16) ----
        for (int i = tid; i < 1024; i += 256) {
            int r = i >> 3, ch = i & 7;
            *(uint4*)(smem + QS + (uint32_t)(r * LDA + ch * 8) * 2) =
                *(const uint4*)(gq + r * Hz + ch * 8);
        }
        __syncthreads();

        uint32_t qf[4][4];
        #pragma unroll
        for (int kc = 0; kc < 4; kc++) {
            uint32_t aoff = (uint32_t)((wr0 + rr + (grp & 1) * 8) * LDA
                                       + kc * 16 + (grp >> 1) * 8) * 2;
            ldsm4(qf[kc], sb + QS + aoff);
        }

        // prologue: stage tile lo
        for (int i = tid; i < 2048; i += 256) {
            int arr = i >> 10, idx = i & 1023;
            int r = idx >> 3, ch = idx & 7;
            const __half* src = arr ? gv : gk;
            cp16(sb + ST0 + arr * 18432 + (uint32_t)(r * LDA + ch * 8) * 2,
                 src + (long)(lo * 128 + r) * Hz + ch * 8);
        }
        cpcommit();

        for (int j = lo; j < hi; j++) {
            uint32_t bufc = sb + ST0 + (uint32_t)((j - lo) & 1) * STG;
            if (j + 1 < hi) {
                uint32_t bufn = sb + ST0 + (uint32_t)((j + 1 - lo) & 1) * STG;
                int jb = (j + 1) * 128;
                for (int i = tid; i < 2048; i += 256) {
                    int arr = i >> 10, idx = i & 1023;
                    int r = idx >> 3, ch = idx & 7;
                    const __half* src = arr ? gv : gk;
                    cp16(bufn + arr * 18432 + (uint32_t)(r * LDA + ch * 8) * 2,
                         src + (long)(jb + r) * Hz + ch * 8);
                }
                cpcommit();
                cpwait<1>();
            } else {
                cpwait<0>();
            }
            __syncthreads();

            #pragma unroll
            for (int half = 0; half < 2; half++) {
                int kb = j * 128 + half * 64;
                if (kb > r0a + 15) break;
                uint32_t rbase = (uint32_t)(half * 64);

                // ---- S = Q K^T ----
                float S[8][4] = {};
                #pragma unroll
                for (int np = 0; np < 4; np++) {
                    #pragma unroll
                    for (int kc = 0; kc < 4; kc++) {
                        uint32_t row = rbase + (uint32_t)(np * 16 + ((grp >> 1) ? 8 : 0) + rr);
                        uint32_t col = (uint32_t)(kc * 16 + (grp & 1) * 8);
                        uint32_t bh[4];
                        ldsm4(bh, bufc + (row * LDA + col) * 2);
                        mma16816(S[np * 2], qf[kc], bh);
                        mma16816(S[np * 2 + 1], qf[kc], bh + 2);
                    }
                }

                // ---- causal mask ----
                int rA = r0a + lane / 4;
                int rB = rA + 8;
                if (kb + 63 > r0a) {
                    #pragma unroll
                    for (int n = 0; n < 8; n++) {
                        int c0 = kb + n * 8 + 2 * (lane % 4);
                        if (c0 > rA)     S[n][0] = -1e30f;
                        if (c0 + 1 > rA) S[n][1] = -1e30f;
                        if (c0 > rB)     S[n][2] = -1e30f;
                        if (c0 + 1 > rB) S[n][3] = -1e30f;
                    }
                }

                // ---- online softmax (exp2 domain) ----
                float mA = -1e30f, mB = -1e30f;
                #pragma unroll
                for (int n = 0; n < 8; n++) {
                    mA = fmaxf(mA, fmaxf(S[n][0], S[n][1]));
                    mB = fmaxf(mB, fmaxf(S[n][2], S[n][3]));
                }
                #pragma unroll
                for (int off = 1; off < 4; off <<= 1) {
                    mA = fmaxf(mA, __shfl_xor_sync(0xffffffffu, mA, off));
                    mB = fmaxf(mB, __shfl_xor_sync(0xffffffffu, mB, off));
                }
                float mnA = fmaxf(mrow[0], mA), mnB = fmaxf(mrow[1], mB);
                float aA = ex2(mrow[0] - mnA), aB = ex2(mrow[1] - mnB);
                mrow[0] = mnA; mrow[1] = mnB;
                float sA = 0.0f, sB = 0.0f;
                #pragma unroll
                for (int n = 0; n < 8; n++) {
                    S[n][0] = ex2(S[n][0] - mnA); sA += S[n][0];
                    S[n][1] = ex2(S[n][1] - mnA); sA += S[n][1];
                    S[n][2] = ex2(S[n][2] - mnB); sB += S[n][2];
                    S[n][3] = ex2(S[n][3] - mnB); sB += S[n][3];
                }
                #pragma unroll
                for (int off = 1; off < 4; off <<= 1) {
                    sA += __shfl_xor_sync(0xffffffffu, sA, off);
                    sB += __shfl_xor_sync(0xffffffffu, sB, off);
                }
                lrow[0] = lrow[0] * aA + sA;
                lrow[1] = lrow[1] * aB + sB;
                #pragma unroll
                for (int n = 0; n < 8; n++) {
                    O[n][0] *= aA; O[n][1] *= aA; O[n][2] *= aB; O[n][3] *= aB;
                }

                // ---- O += P V ----
                #pragma unroll
                for (int kc = 0; kc < 4; kc++) {
                    int t0 = 2 * kc, t1 = 2 * kc + 1;
                    uint32_t ph[4];
                    ph[0] = packh2(S[t0][0], S[t0][1]);
                    ph[1] = packh2(S[t0][2], S[t0][3]);
                    ph[2] = packh2(S[t1][0], S[t1][1]);
                    ph[3] = packh2(S[t1][2], S[t1][3]);
                    #pragma unroll
                    for (int np = 0; np < 4; np++) {
                        uint32_t row = rbase + (uint32_t)(kc * 16 + ((grp & 1) ? 8 : 0) + rr);
                        uint32_t col = (uint32_t)(np * 16 + (grp >> 1) * 8);
                        uint32_t vh[4];
                        ldsm4t(vh, bufc + 18432 + (row * LDA + col) * 2);
                        mma16816(O[np * 2], ph, vh);
                        mma16816(O[np * 2 + 1], ph, vh + 2);
                    }
                }
            }
            __syncthreads();
        }
    }

    // ---- write partial (unnormalized O, m, l) ----
    long prow = ((long)(part * Bz + b)) * Tz + r0a + lane / 4;
    long prB = prow + 8;
    int cb = 2 * (lane % 4);
    #pragma unroll
    for (int n = 0; n < 8; n++) {
        *(float2*)&g_po[prow * Hz + n * 8 + cb] = make_float2(O[n][0], O[n][1]);
        *(float2*)&g_po[prB * Hz + n * 8 + cb] = make_float2(O[n][2], O[n][3]);
    }
    if ((lane & 3) == 0) {
        g_pm[prow] = mrow[0];
        g_pm[prB]  = mrow[1];
        g_pl[prow] = lrow[0];
        g_pl[prB]  = lrow[1];
    }
}

// ---------------------------------------------------------------------------
// combine: merge the two split-K partials. grid 2048 x 256 threads,
// thread handles 4 cols of one row.
// ---------------------------------------------------------------------------
__global__ void combine_kernel(float* __restrict__ out) {
    int idx = blockIdx.x * 256 + threadIdx.x;   // 524288 total
    int c4 = (idx & 15) * 4;
    long row = idx >> 4;                         // b*Tz + t
    float m0 = g_pm[row], m1 = g_pm[Bz * Tz + row];
    float l0 = g_pl[row], l1 = g_pl[Bz * Tz + row];
    float ms = fmaxf(m0, m1);
    float a0 = ex2(m0 - ms), a1 = ex2(m1 - ms);
    float inv = 1.0f / (l0 * a0 + l1 * a1);
    float4 o0 = *(const float4*)&g_po[row * Hz + c4];
    float4 o1 = *(const float4*)&g_po[(long)Bz * Tz * Hz + row * Hz + c4];
    float4 r;
    r.x = (o0.x * a0 + o1.x * a1) * inv;
    r.y = (o0.y * a0 + o1.y * a1) * inv;
    r.z = (o0.z * a0 + o1.z * a1) * inv;
    r.w = (o0.w * a0 + o1.w * a1) * inv;
    *(float4*)&out[row * Hz + c4] = r;
}

extern "C" void kernel_launch(void* const* d_in, const int* in_sizes, int n_in,
                              void* d_out, int out_size) {
    const float* x  = (const float*)d_in[0];
    const float* Wk = (const float*)d_in[1];
    const float* Wq = (const float*)d_in[2];
    const float* Wv = (const float*)d_in[3];
    float* out = (float*)d_out;

    prep_kernel<<<48, 256>>>(Wk, Wq, Wv);

    cudaFuncSetAttribute(proj_kernel,
                         cudaFuncAttributeMaxDynamicSharedMemorySize, PSMEM);
    proj_kernel<<<(Bz * Tz) / 128, 256, PSMEM>>>(x);

    cudaFuncSetAttribute(attn_kernel,
                         cudaFuncAttributeMaxDynamicSharedMemorySize, ASMEM);
    dim3 ag(64, Bz);
    attn_kernel<<<ag, 256, ASMEM>>>();

    combine_kernel<<<2048, 256>>>(out);
}